// round 14
// baseline (speedup 1.0000x reference)
#include <cuda_runtime.h>
#include <math.h>
#include <stdint.h>

#define KMAX 64
#define BUF  16
#define NLVL 5          // levels 3..7
#define NB   (NLVL * KMAX)
#define NTHR_A 256      // assign block (small => many blocks => dynamic balance)
#define MAXBLK_A 512    // upper bound on assign grid
#define NTHR_T 64       // tasks block: 2 warps (R5-measured fastest geometry layout)
#define NTASK (2 * KMAX)
#define FULLM 0xffffffffu

// ---------------- device-global state (zero-init; g_best restored by k_final) ----------------
__device__ unsigned long long g_best[2][NB];     // INVERTED packed keys; 0 = empty (max-reduced)
__device__ int    g_k2b[KMAX];                   // original k -> bucket slot
__device__ int    g_cnt01[2];
__device__ double g_blk_lse[MAXBLK_A];
__device__ double g_corr_val;
__device__ double g_task_gl[2][KMAX];
__device__ double g_task_oob[2][KMAX];

__device__ __forceinline__ float f_inf() { return __int_as_float(0x7f800000); }

// Non-FMA cross product: matches XLA's unfused mul/sub semantics exactly.
__device__ __forceinline__ float cross_nf(float ax, float ay, float bx, float by)
{
    return __fsub_rn(__fmul_rn(ax, by), __fmul_rn(ay, bx));
}

// ---------------- geometry helpers (R4/R5 2-warp versions, bit-exact, measured fast) ----------------
__device__ float shoelace16(const float2* V, int c)
{
    float s = 0.f;
    #pragma unroll
    for (int i = 0; i < BUF; i++) {
        if (i >= c) continue;
        int nxt = (i + 1 < c) ? i + 1 : 0;
        s = __fadd_rn(s, cross_nf(V[i].x, V[i].y, V[nxt].x, V[nxt].y));
    }
    return 0.5f * fabsf(s);
}

// lane-per-vertex membership + stable sort; reference semantics, bit-exact (R4/R5)
__device__ int hull_warp_sorted(const float2* sP, int n, float* skey, float2* sV, int lane)
{
    bool h = false;
    if (lane < n) {
        float pix = sP[lane].x, piy = sP[lane].y;
        for (int j = 0; j < n && !h; j++) {
            if (j == lane) continue;
            float dx = __fsub_rn(sP[j].x, pix), dy = __fsub_rn(sP[j].y, piy);
            float mn = f_inf();
            for (int k = 0; k < n; k++) {
                float cr = cross_nf(dx, dy, __fsub_rn(sP[k].x, pix), __fsub_rn(sP[k].y, piy));
                mn = fminf(mn, cr);            // min: order-independent
            }
            if (mn >= -1e-6f) h = true;
        }
    }
    unsigned mask = __ballot_sync(FULLM, h);
    int cnt = __popc(mask);
    float sx = 0.f, sy = 0.f;
    for (int i = 0; i < n; i++)
        if ((mask >> i) & 1) { sx = __fadd_rn(sx, sP[i].x); sy = __fadd_rn(sy, sP[i].y); }
    float cd = (float)(cnt > 0 ? cnt : 1);
    float cenx = __fdiv_rn(sx, cd), ceny = __fdiv_rn(sy, cd);
    if (lane < n)
        skey[lane] = h ? atan2f(__fsub_rn(sP[lane].y, ceny), __fsub_rn(sP[lane].x, cenx))
                       : f_inf();
    __syncwarp();
    if (lane < n) {                                    // stable rank == argsort (R6+)
        float ki = skey[lane];
        int r = 0;
        for (int j = 0; j < n; j++) {
            float kj = skey[j];
            r += (kj < ki) || (kj == ki && j < lane);
        }
        sV[r] = sP[lane];
    }
    if (lane >= n && lane < BUF) sV[lane] = make_float2(0.f, 0.f);
    __syncwarp();
    return cnt;
}

__device__ void clip_warp(float2* V, int& c, float2 a, float2 b, int lane, float2* scratch)
{
    float ex = __fsub_rn(b.x, a.x), ey = __fsub_rn(b.y, a.y);
    int cc = c;
    bool active = (lane < BUF) && (lane < cc);
    int nxt = (lane + 1 < cc) ? lane + 1 : 0;
    float2 cur = active ? V[lane] : make_float2(0.f, 0.f);
    float2 nx  = active ? V[nxt]  : make_float2(0.f, 0.f);
    float s_cur = cross_nf(ex, ey, __fsub_rn(cur.x, a.x), __fsub_rn(cur.y, a.y));
    float s_nxt = cross_nf(ex, ey, __fsub_rn(nx.x,  a.x), __fsub_rn(nx.y,  a.y));
    bool in_cur = s_cur >= 0.f, in_nxt = s_nxt >= 0.f;
    float den = __fsub_rn(s_cur, s_nxt);
    float t = (fabsf(den) > 1e-9f) ? __fdiv_rn(s_cur, den) : 0.f;
    float2 ipt = make_float2(__fadd_rn(cur.x, __fmul_rn(t, __fsub_rn(nx.x, cur.x))),
                             __fadd_rn(cur.y, __fmul_rn(t, __fsub_rn(nx.y, cur.y))));
    bool f_int = active && (in_cur != in_nxt);
    bool f_nxt = active && in_nxt;
    unsigned bi = __ballot_sync(FULLM, f_int);
    unsigned bn = __ballot_sync(FULLM, f_nxt);
    unsigned below = (1u << lane) - 1u;
    int pos_i = __popc(bi & below) + __popc(bn & below);
    int pos_n = pos_i + (f_int ? 1 : 0);
    int nc = __popc(bi) + __popc(bn);
    __syncwarp();
    if (f_int && pos_i < BUF) scratch[pos_i] = ipt;
    if (f_nxt && pos_n < BUF) scratch[pos_n] = nx;
    __syncwarp();
    if (lane < BUF) V[lane] = (lane < nc) ? scratch[lane] : make_float2(0.f, 0.f);
    __syncwarp();
    c = nc;
}

__device__ __forceinline__ double lse_term(const float4* c4q)
{
    float v[16];
    #pragma unroll
    for (int j = 0; j < 4; j++) {
        float4 f = c4q[j];
        v[4 * j] = f.x; v[4 * j + 1] = f.y; v[4 * j + 2] = f.z; v[4 * j + 3] = f.w;
    }
    float mm = v[0];
    #pragma unroll
    for (int j = 1; j < 16; j++) mm = fmaxf(mm, v[j]);
    float ss = 0.f;
    #pragma unroll
    for (int j = 0; j < 16; j++) ss += __expf(v[j] - mm);
    return (double)((mm + __logf(ss)) - v[0]);
}

// ================= kernel 1: prep + assign + cls logsumexp (R12/13, measured fast) =================
__global__ void __launch_bounds__(NTHR_A) k_assign(
    const float* __restrict__ rpi, const float* __restrict__ rpr,
    const float* __restrict__ cls, const float* __restrict__ pstr,
    const float* __restrict__ gtb, int N, int K)
{
    __shared__ float  s_cx[KMAX], s_cy[KMAX], s_rw[KMAX], s_rh[KMAX];
    __shared__ int    s_lvl[KMAX];
    __shared__ float4 s_bkt[NB];
    __shared__ int    s_k2b[KMAX];
    __shared__ int    s_cnt[NLVL];
    __shared__ double s_red[NTHR_A / 32];

    const int tid  = threadIdx.x;
    const int bid  = blockIdx.x;
    const int lane = tid & 31;
    const int w    = tid >> 5;

    if (tid < K) {
        const float* r = gtb + 8 * tid;
        float xmn = fminf(fminf(r[0], r[2]), fminf(r[4], r[6]));
        float xmx = fmaxf(fmaxf(r[0], r[2]), fmaxf(r[4], r[6]));
        float ymn = fminf(fminf(r[1], r[3]), fminf(r[5], r[7]));
        float ymx = fmaxf(fmaxf(r[1], r[3]), fmaxf(r[5], r[7]));
        float ww = fmaxf(__fsub_rn(xmx, xmn), 1e-6f);
        float hh = fmaxf(__fsub_rn(ymx, ymn), 1e-6f);
        s_cx[tid] = __fmul_rn(__fadd_rn(xmn, xmx), 0.5f);
        s_cy[tid] = __fmul_rn(__fadd_rn(ymn, ymx), 0.5f);
        s_rw[tid] = __fdiv_rn(1.0f, ww);
        s_rh[tid] = __fdiv_rn(1.0f, hh);
        float lv = __fmul_rn(__fadd_rn(log2f(__fdiv_rn(ww, 4.0f)),
                                       log2f(__fdiv_rn(hh, 4.0f))), 0.5f);
        int lvl = (int)lv;
        s_lvl[tid] = max(3, min(7, lvl));
    }
    __syncthreads();
    if (tid == 0) {                                  // serial bucket build, ascending k
        int cnt[NLVL];
        #pragma unroll
        for (int l = 0; l < NLVL; l++) cnt[l] = 0;
        for (int q = 0; q < K; q++) {
            int li = s_lvl[q] - 3;
            int slot = li * KMAX + cnt[li];
            s_bkt[slot] = make_float4(s_cx[q], s_cy[q], s_rw[q], s_rh[q]);
            s_k2b[q] = slot;
            cnt[li]++;
        }
        #pragma unroll
        for (int l = 0; l < NLVL; l++) s_cnt[l] = cnt[l];
    }
    __syncthreads();
    if (bid == 0 && tid < K) g_k2b[tid] = s_k2b[tid];   // publish map for k_tasks

    const int n = bid * NTHR_A + tid;
    const bool act = (n < N);
    const int i0 = act ? n : 0;

    // hoisted loads (clamped): stream while the gt loop computes
    float  st = __ldg(pstr + i0);
    float2 pi = __ldg((const float2*)(rpi + (size_t)i0 * 18 + 8));
    float2 pr = __ldg((const float2*)(rpr + (size_t)i0 * 18 + 8));
    float4 cq[4];
    {
        const float4* q = (const float4*)(cls + (size_t)i0 * 16);
        #pragma unroll
        for (int j = 0; j < 4; j++) cq[j] = __ldg(q + j);
    }
    int li = (31 - __clz((int)st)) - 3;

    unsigned actmask = __ballot_sync(FULLM, act);
    if (actmask) {
        int src0 = __ffs(actmask) - 1;
        int uli = __shfl_sync(FULLM, li, src0);
        bool uniform = __all_sync(FULLM, !act || (li == uli));
        unsigned warp_n0 = (unsigned)(n - lane);     // consecutive n within warp
        if (uniform) {
            int cnt = s_cnt[uli], base = uli * KMAX;
            for (int m = 0; m < cnt; m++) {
                int slot = base + m;
                float4 gq = s_bkt[slot];
                unsigned di = 0xffffffffu, dr = 0xffffffffu;
                if (act) {
                    float dxi = __fmul_rn(__fsub_rn(pi.x, gq.x), gq.z);
                    float dyi = __fmul_rn(__fsub_rn(pi.y, gq.y), gq.w);
                    di = __float_as_uint(__fadd_rn(__fmul_rn(dxi, dxi), __fmul_rn(dyi, dyi)));
                    float dxr = __fmul_rn(__fsub_rn(pr.x, gq.x), gq.z);
                    float dyr = __fmul_rn(__fsub_rn(pr.y, gq.y), gq.w);
                    dr = __float_as_uint(__fadd_rn(__fmul_rn(dxr, dxr), __fmul_rn(dyr, dyr)));
                }
                unsigned mi = __reduce_min_sync(FULLM, di);
                unsigned mr = __reduce_min_sync(FULLM, dr);
                unsigned bi = __ballot_sync(FULLM, di == mi);
                unsigned br = __ballot_sync(FULLM, dr == mr);
                if (lane == 0) {
                    unsigned uni_ = warp_n0 + (unsigned)(__ffs(bi) - 1);
                    unsigned unr_ = warp_n0 + (unsigned)(__ffs(br) - 1);
                    atomicMax(&g_best[0][slot], ~(((unsigned long long)mi << 32) | uni_));
                    atomicMax(&g_best[1][slot], ~(((unsigned long long)mr << 32) | unr_));
                }
            }
        } else if (act) {                            // level-boundary warps (rare)
            int cnt = s_cnt[li], base = li * KMAX;
            unsigned un = (unsigned)n;
            for (int m = 0; m < cnt; m++) {
                int slot = base + m;
                float4 gq = s_bkt[slot];
                float dxi = __fmul_rn(__fsub_rn(pi.x, gq.x), gq.z);
                float dyi = __fmul_rn(__fsub_rn(pi.y, gq.y), gq.w);
                float ddi = __fadd_rn(__fmul_rn(dxi, dxi), __fmul_rn(dyi, dyi));
                atomicMax(&g_best[0][slot],
                          ~(((unsigned long long)__float_as_uint(ddi) << 32) | un));
                float dxr = __fmul_rn(__fsub_rn(pr.x, gq.x), gq.z);
                float dyr = __fmul_rn(__fsub_rn(pr.y, gq.y), gq.w);
                float ddr = __fadd_rn(__fmul_rn(dxr, dxr), __fmul_rn(dyr, dyr));
                atomicMax(&g_best[1][slot],
                          ~(((unsigned long long)__float_as_uint(ddr) << 32) | un));
            }
        }
    }
    double lterm = act ? lse_term(cq) : 0.0;
    for (int o = 16; o; o >>= 1) lterm += __shfl_down_sync(FULLM, lterm, o);
    if (lane == 0) s_red[w] = lterm;
    __syncthreads();
    if (tid == 0) {
        double bs = 0.0;
        for (int q = 0; q < NTHR_A / 32; q++) bs += s_red[q];
        g_blk_lse[bid] = bs;
    }
}

// ================= kernel 2: per-block replay + corr + 2-warp geometry =================
__global__ void __launch_bounds__(NTHR_T, 1) k_tasks(
    const float* __restrict__ rpi, const float* __restrict__ rpr,
    const float* __restrict__ cls, const float* __restrict__ gtb,
    const int* __restrict__ glab, int K)
{
    __shared__ unsigned long long s_cmp[KMAX];
    __shared__ int s_j[KMAX];
    __shared__ int s_lead[KMAX];
    __shared__ int s_pidx[KMAX], s_pgt[KMAX];
    __shared__ int s_npos;
    __shared__ double s_red[2];
    __shared__ float2 sP9[9];
    __shared__ float2 sGT[4];
    __shared__ float2 sG[4];
    __shared__ float2 sPtsB[13];
    __shared__ float2 sVa[BUF], sVb[BUF];
    __shared__ float2 sScrA[BUF];
    __shared__ float  sKeyA[13], sKeyB[13], sKeyG[4];
    __shared__ float  s_apred, s_agt, s_aint, s_ahull;

    const int tid  = threadIdx.x;
    const int bid  = blockIdx.x;
    const int lane = tid & 31;
    const int w    = tid >> 5;
    const int s = (bid >= KMAX) ? 1 : 0;
    const int m = bid - s * KMAX;

    // replay stage s (order-independent reformulation, validated rounds 6-13)
    {
        unsigned long long v = (tid < K) ? __ldcg(&g_best[s][__ldg(&g_k2b[tid])]) : 0ull;
        bool valid = (v != 0ull);
        unsigned long long pk = ~v;              // (md_bits<<32)|point_idx
        s_j[tid]   = valid ? (int)(unsigned)(pk & 0xffffffffu) : (-1 - tid);
        s_cmp[tid] = valid ? (((pk >> 32) << 32) | (unsigned)tid) : ~0ull;
    }
    __syncthreads();
    {
        int j = s_j[tid];
        bool lead = (j >= 0);
        if (lead)
            for (int e = 0; e < tid; e++)
                if (s_j[e] == j) { lead = false; break; }
        s_lead[tid] = lead ? 1 : 0;
    }
    __syncthreads();
    if (tid < K && s_lead[tid]) {
        int j = s_j[tid];
        unsigned long long best = s_cmp[tid];
        for (int e = 0; e < K; e++)
            if (s_j[e] == j && s_cmp[e] < best) best = s_cmp[e];
        int pos = 0;
        for (int e = 0; e < tid; e++) pos += s_lead[e];
        s_pidx[pos] = j;
        s_pgt[pos]  = (int)(unsigned)(best & 0xffffffffu);
    }
    __syncthreads();
    if (tid == 0) {
        int cnt = 0;
        for (int e = 0; e < K; e++) cnt += s_lead[e];
        s_npos = cnt;
        if (m == 0) g_cnt01[s] = cnt;            // blocks 0 and KMAX publish counts
    }
    __syncthreads();

    // block KMAX (stage 1, m==0): cls label correction, overlapped with other blocks' geometry
    if (bid == KMAX) {
        double part = 0.0;
        if (tid < s_npos) {
            int j   = s_pidx[tid];
            int lab = glab[s_pgt[tid]];
            part = (double)cls[(size_t)j * 16 + 0] - (double)cls[(size_t)j * 16 + lab];
        }
        for (int o = 16; o; o >>= 1) part += __shfl_down_sync(FULLM, part, o);
        if (lane == 0) s_red[w] = part;
        __syncthreads();
        if (tid == 0) g_corr_val = s_red[0] + s_red[1];
    }

    if (m >= s_npos) return;

    const float* rp  = s ? rpr : rpi;
    {
        int j  = s_pidx[m];
        int gi = s_pgt[m];
        const float* g8  = gtb + 8 * gi;
        const float* p18 = rp + (size_t)j * 18;
        if (tid < 4) {
            float2 c = make_float2(g8[2 * tid], g8[2 * tid + 1]);
            sGT[tid] = c;
            sPtsB[tid] = c;
        }
        if (tid >= 4 && tid < 13) {
            float2 c = make_float2(p18[2 * (tid - 4)], p18[2 * (tid - 4) + 1]);
            sP9[tid - 4] = c;
            sPtsB[tid] = c;
        }
    }
    __syncthreads();

    if (w == 1) {
        // big hull of concat(gt4_original, p9)
        int ch = hull_warp_sorted(sPtsB, 13, sKeyB, sVb, lane);
        if (lane == 0) s_ahull = shoelace16(sVb, ch);
    } else {
        // gt CCW ordering by angle around mean, stable rank (== argsort)
        if (lane < 4) {
            float cmx = (sGT[0].x + sGT[1].x + sGT[2].x + sGT[3].x) * 0.25f;
            float cmy = (sGT[0].y + sGT[1].y + sGT[2].y + sGT[3].y) * 0.25f;
            sKeyG[lane] = atan2f(__fsub_rn(sGT[lane].y, cmy),
                                 __fsub_rn(sGT[lane].x, cmx));
        }
        __syncwarp();
        if (lane < 4) {
            float ki = sKeyG[lane];
            int r = 0;
            #pragma unroll
            for (int j2 = 0; j2 < 4; j2++) {
                float kj = sKeyG[j2];
                r += (kj < ki) || (kj == ki && j2 < lane);
            }
            sG[r] = sGT[lane];
        }
        __syncwarp();
        // pred hull + clip
        int c = hull_warp_sorted(sP9, 9, sKeyA, sVa, lane);
        if (lane == 0) {
            s_apred = shoelace16(sVa, c);
            float sgt = 0.f;
            #pragma unroll
            for (int i = 0; i < 4; i++) {
                int nx = (i + 1 < 4) ? i + 1 : 0;
                sgt = __fadd_rn(sgt, cross_nf(sG[i].x, sG[i].y, sG[nx].x, sG[nx].y));
            }
            s_agt = 0.5f * fabsf(sgt);
        }
        for (int e = 0; e < 4; e++) clip_warp(sVa, c, sG[e], sG[(e + 1) & 3], lane, sScrA);
        if (lane == 0) s_aint = shoelace16(sVa, c);
    }
    __syncthreads();

    if (tid == 0) {
        float uni = __fsub_rn(__fadd_rn(s_apred, s_agt), s_aint);
        float iou = __fdiv_rn(s_aint, __fadd_rn(uni, 1e-16f));
        float giou = __fsub_rn(iou, __fdiv_rn(__fsub_rn(s_ahull, uni),
                                              __fadd_rn(s_ahull, 1e-16f)));
        float gl = __fsub_rn(1.0f, giou);

        // out-of-box penalty (serial: matches reference reduce order)
        float acc = 0.f;
        #pragma unroll
        for (int p = 0; p < 9; p++) {
            float mx = -f_inf();
            #pragma unroll
            for (int e = 0; e < 4; e++) {
                float ex = __fsub_rn(sG[(e + 1) & 3].x, sG[e].x);
                float ey = __fsub_rn(sG[(e + 1) & 3].y, sG[e].y);
                float num = cross_nf(ex, ey, __fsub_rn(sP9[p].x, sG[e].x),
                                             __fsub_rn(sP9[p].y, sG[e].y));
                float sv = __fdiv_rn(num,
                    __fadd_rn(__fsqrt_rn(__fadd_rn(__fmul_rn(ex, ex),
                                                   __fmul_rn(ey, ey))), 1e-9f));
                mx = fmaxf(mx, -sv);
            }
            acc = __fadd_rn(acc, fmaxf(mx, 0.f));
        }
        g_task_gl[s][m]  = (double)gl;
        g_task_oob[s][m] = (double)__fdiv_rn(acc, 9.0f);
    }
}

// ================= kernel 3: final combine + state restore =================
__global__ void k_final(int N, int nblk_a, float* __restrict__ out)
{
    __shared__ double s_tgl[2 * KMAX], s_tob[2 * KMAX];
    __shared__ double s_lse[MAXBLK_A];
    const int tid = threadIdx.x;
    const int nt  = blockDim.x;

    int c0 = __ldcg(&g_cnt01[0]);
    int c1 = __ldcg(&g_cnt01[1]);
    for (int q = tid; q < 2 * KMAX; q += nt) {
        int s2 = q >> 6, mm = q & 63;
        int cs = s2 ? c1 : c0;
        s_tgl[q] = (mm < cs) ? __ldcg(&g_task_gl[s2][mm])  : 0.0;
        s_tob[q] = (mm < cs) ? __ldcg(&g_task_oob[s2][mm]) : 0.0;
    }
    for (int q = tid; q < nblk_a; q += nt) s_lse[q] = __ldcg(&g_blk_lse[q]);
    __syncthreads();
    if (tid == 0) {
        double lse = 0.0;
        for (int q = 0; q < nblk_a; q++) lse += s_lse[q];          // fixed order
        double loc_i = 0.0, sc_i = 0.0, loc_r = 0.0, sc_r = 0.0;
        for (int mm = 0; mm < KMAX; mm++) { loc_i += s_tgl[mm];        sc_i += s_tob[mm]; }
        for (int mm = 0; mm < KMAX; mm++) { loc_r += s_tgl[KMAX + mm]; sc_r += s_tob[KMAX + mm]; }
        double corr = __ldcg(&g_corr_val);
        double cls_loss = (lse + corr) / (double)N;
        double ni = (double)max(c0, 1);
        double nr = (double)max(c1, 1);
        double loss = cls_loss
                    + 0.3  * (loc_i / ni)
                    + 1.0  * (loc_r / nr)
                    + 0.05 * (sc_i / ni)
                    + 0.1  * (sc_r / nr);
        out[0] = (float)loss;
    }
    // restore zero-init g_best for the next (identical) launch
    for (int q = tid; q < NB; q += nt) { g_best[0][q] = 0ull; g_best[1][q] = 0ull; }
}

// ---------------- launch ----------------
extern "C" void kernel_launch(void* const* d_in, const int* in_sizes, int n_in,
                              void* d_out, int out_size)
{
    const float* rpi  = (const float*)d_in[0];
    const float* rpr  = (const float*)d_in[1];
    const float* cls  = (const float*)d_in[2];
    const float* pstr = (const float*)d_in[3];
    const float* gtb  = (const float*)d_in[4];
    const int*   glab = (const int*)d_in[5];
    float* out = (float*)d_out;

    int N = in_sizes[3];          // points_stride element count
    int K = in_sizes[5];          // gt_labels element count (=64)
    if (K > KMAX) K = KMAX;

    int nblk_a = (N + NTHR_A - 1) / NTHR_A;     // one chunk per block
    if (nblk_a > MAXBLK_A) nblk_a = MAXBLK_A;   // (N fits: 98208/256 = 384)

    k_assign<<<nblk_a, NTHR_A>>>(rpi, rpr, cls, pstr, gtb, N, K);
    k_tasks<<<NTASK, NTHR_T>>>(rpi, rpr, cls, gtb, glab, K);
    k_final<<<1, 256>>>(N, nblk_a, out);
}

// round 15
// speedup vs baseline: 1.0048x; 1.0048x over previous
#include <cuda_runtime.h>
#include <math.h>
#include <stdint.h>

#define KMAX 64
#define BUF  16
#define NLVL 5          // levels 3..7
#define NB   (NLVL * KMAX)
#define NTHR_A 256      // assign block (small => many blocks => dynamic balance)
#define MAXBLK_A 512    // upper bound on assign grid
#define NTHR_G 64       // geom block: 2 warps (R5-measured fastest)
#define NTASK (2 * KMAX)
#define FULLM 0xffffffffu

// ---------------- device-global state (zero-init; g_best restored by k_final) ----------------
__device__ unsigned long long g_best[2][NB];     // INVERTED packed keys; 0 = empty (max-reduced)
__device__ int    g_k2b[KMAX];                   // original k -> bucket slot
__device__ int    g_pos_idx[2][KMAX];
__device__ int    g_pos_gt[2][KMAX];
__device__ int    g_cnt01[2];
__device__ double g_blk_lse[MAXBLK_A];
__device__ double g_corr_val;
__device__ double g_task_gl[2][KMAX];
__device__ double g_task_oob[2][KMAX];

__device__ __forceinline__ float f_inf() { return __int_as_float(0x7f800000); }

// Non-FMA cross product: matches XLA's unfused mul/sub semantics exactly.
__device__ __forceinline__ float cross_nf(float ax, float ay, float bx, float by)
{
    return __fsub_rn(__fmul_rn(ax, by), __fmul_rn(ay, bx));
}

// ---------------- geometry helpers (R5 2-warp versions, bit-exact, measured fast) ----------------
__device__ float shoelace16(const float2* V, int c)
{
    float s = 0.f;
    #pragma unroll
    for (int i = 0; i < BUF; i++) {
        if (i >= c) continue;
        int nxt = (i + 1 < c) ? i + 1 : 0;
        s = __fadd_rn(s, cross_nf(V[i].x, V[i].y, V[nxt].x, V[nxt].y));
    }
    return 0.5f * fabsf(s);
}

// lane-per-vertex membership + stable rank sort; reference semantics, bit-exact
__device__ int hull_warp_sorted(const float2* sP, int n, float* skey, float2* sV, int lane)
{
    bool h = false;
    if (lane < n) {
        float pix = sP[lane].x, piy = sP[lane].y;
        for (int j = 0; j < n && !h; j++) {
            if (j == lane) continue;
            float dx = __fsub_rn(sP[j].x, pix), dy = __fsub_rn(sP[j].y, piy);
            float mn = f_inf();
            for (int k = 0; k < n; k++) {
                float cr = cross_nf(dx, dy, __fsub_rn(sP[k].x, pix), __fsub_rn(sP[k].y, piy));
                mn = fminf(mn, cr);            // min: order-independent
            }
            if (mn >= -1e-6f) h = true;
        }
    }
    unsigned mask = __ballot_sync(FULLM, h);
    int cnt = __popc(mask);
    float sx = 0.f, sy = 0.f;
    for (int i = 0; i < n; i++)
        if ((mask >> i) & 1) { sx = __fadd_rn(sx, sP[i].x); sy = __fadd_rn(sy, sP[i].y); }
    float cd = (float)(cnt > 0 ? cnt : 1);
    float cenx = __fdiv_rn(sx, cd), ceny = __fdiv_rn(sy, cd);
    if (lane < n)
        skey[lane] = h ? atan2f(__fsub_rn(sP[lane].y, ceny), __fsub_rn(sP[lane].x, cenx))
                       : f_inf();
    __syncwarp();
    if (lane < n) {                                    // stable rank == argsort
        float ki = skey[lane];
        int r = 0;
        for (int j = 0; j < n; j++) {
            float kj = skey[j];
            r += (kj < ki) || (kj == ki && j < lane);
        }
        sV[r] = sP[lane];
    }
    if (lane >= n && lane < BUF) sV[lane] = make_float2(0.f, 0.f);
    __syncwarp();
    return cnt;
}

__device__ void clip_warp(float2* V, int& c, float2 a, float2 b, int lane, float2* scratch)
{
    float ex = __fsub_rn(b.x, a.x), ey = __fsub_rn(b.y, a.y);
    int cc = c;
    bool active = (lane < BUF) && (lane < cc);
    int nxt = (lane + 1 < cc) ? lane + 1 : 0;
    float2 cur = active ? V[lane] : make_float2(0.f, 0.f);
    float2 nx  = active ? V[nxt]  : make_float2(0.f, 0.f);
    float s_cur = cross_nf(ex, ey, __fsub_rn(cur.x, a.x), __fsub_rn(cur.y, a.y));
    float s_nxt = cross_nf(ex, ey, __fsub_rn(nx.x,  a.x), __fsub_rn(nx.y,  a.y));
    bool in_cur = s_cur >= 0.f, in_nxt = s_nxt >= 0.f;
    float den = __fsub_rn(s_cur, s_nxt);
    float t = (fabsf(den) > 1e-9f) ? __fdiv_rn(s_cur, den) : 0.f;
    float2 ipt = make_float2(__fadd_rn(cur.x, __fmul_rn(t, __fsub_rn(nx.x, cur.x))),
                             __fadd_rn(cur.y, __fmul_rn(t, __fsub_rn(nx.y, cur.y))));
    bool f_int = active && (in_cur != in_nxt);
    bool f_nxt = active && in_nxt;
    unsigned bi = __ballot_sync(FULLM, f_int);
    unsigned bn = __ballot_sync(FULLM, f_nxt);
    unsigned below = (1u << lane) - 1u;
    int pos_i = __popc(bi & below) + __popc(bn & below);
    int pos_n = pos_i + (f_int ? 1 : 0);
    int nc = __popc(bi) + __popc(bn);
    __syncwarp();
    if (f_int && pos_i < BUF) scratch[pos_i] = ipt;
    if (f_nxt && pos_n < BUF) scratch[pos_n] = nx;
    __syncwarp();
    if (lane < BUF) V[lane] = (lane < nc) ? scratch[lane] : make_float2(0.f, 0.f);
    __syncwarp();
    c = nc;
}

__device__ __forceinline__ double lse_term(const float4* c4q)
{
    float v[16];
    #pragma unroll
    for (int j = 0; j < 4; j++) {
        float4 f = c4q[j];
        v[4 * j] = f.x; v[4 * j + 1] = f.y; v[4 * j + 2] = f.z; v[4 * j + 3] = f.w;
    }
    float mm = v[0];
    #pragma unroll
    for (int j = 1; j < 16; j++) mm = fmaxf(mm, v[j]);
    float ss = 0.f;
    #pragma unroll
    for (int j = 0; j < 16; j++) ss += __expf(v[j] - mm);
    return (double)((mm + __logf(ss)) - v[0]);
}

// ================= kernel 1: prep + assign + cls logsumexp (R14 verbatim) =================
__global__ void __launch_bounds__(NTHR_A) k_assign(
    const float* __restrict__ rpi, const float* __restrict__ rpr,
    const float* __restrict__ cls, const float* __restrict__ pstr,
    const float* __restrict__ gtb, int N, int K)
{
    __shared__ float  s_cx[KMAX], s_cy[KMAX], s_rw[KMAX], s_rh[KMAX];
    __shared__ int    s_lvl[KMAX];
    __shared__ float4 s_bkt[NB];
    __shared__ int    s_k2b[KMAX];
    __shared__ int    s_cnt[NLVL];
    __shared__ double s_red[NTHR_A / 32];

    const int tid  = threadIdx.x;
    const int bid  = blockIdx.x;
    const int lane = tid & 31;
    const int w    = tid >> 5;

    if (tid < K) {
        const float* r = gtb + 8 * tid;
        float xmn = fminf(fminf(r[0], r[2]), fminf(r[4], r[6]));
        float xmx = fmaxf(fmaxf(r[0], r[2]), fmaxf(r[4], r[6]));
        float ymn = fminf(fminf(r[1], r[3]), fminf(r[5], r[7]));
        float ymx = fmaxf(fmaxf(r[1], r[3]), fmaxf(r[5], r[7]));
        float ww = fmaxf(__fsub_rn(xmx, xmn), 1e-6f);
        float hh = fmaxf(__fsub_rn(ymx, ymn), 1e-6f);
        s_cx[tid] = __fmul_rn(__fadd_rn(xmn, xmx), 0.5f);
        s_cy[tid] = __fmul_rn(__fadd_rn(ymn, ymx), 0.5f);
        s_rw[tid] = __fdiv_rn(1.0f, ww);
        s_rh[tid] = __fdiv_rn(1.0f, hh);
        float lv = __fmul_rn(__fadd_rn(log2f(__fdiv_rn(ww, 4.0f)),
                                       log2f(__fdiv_rn(hh, 4.0f))), 0.5f);
        int lvl = (int)lv;
        s_lvl[tid] = max(3, min(7, lvl));
    }
    __syncthreads();
    if (tid == 0) {                                  // serial bucket build, ascending k
        int cnt[NLVL];
        #pragma unroll
        for (int l = 0; l < NLVL; l++) cnt[l] = 0;
        for (int q = 0; q < K; q++) {
            int li = s_lvl[q] - 3;
            int slot = li * KMAX + cnt[li];
            s_bkt[slot] = make_float4(s_cx[q], s_cy[q], s_rw[q], s_rh[q]);
            s_k2b[q] = slot;
            cnt[li]++;
        }
        #pragma unroll
        for (int l = 0; l < NLVL; l++) s_cnt[l] = cnt[l];
    }
    __syncthreads();
    if (bid == 0 && tid < K) g_k2b[tid] = s_k2b[tid];   // publish map for k_scan

    const int n = bid * NTHR_A + tid;
    const bool act = (n < N);
    const int i0 = act ? n : 0;

    // hoisted loads (clamped): stream while the gt loop computes
    float  st = __ldg(pstr + i0);
    float2 pi = __ldg((const float2*)(rpi + (size_t)i0 * 18 + 8));
    float2 pr = __ldg((const float2*)(rpr + (size_t)i0 * 18 + 8));
    float4 cq[4];
    {
        const float4* q = (const float4*)(cls + (size_t)i0 * 16);
        #pragma unroll
        for (int j = 0; j < 4; j++) cq[j] = __ldg(q + j);
    }
    int li = (31 - __clz((int)st)) - 3;

    unsigned actmask = __ballot_sync(FULLM, act);
    if (actmask) {
        int src0 = __ffs(actmask) - 1;
        int uli = __shfl_sync(FULLM, li, src0);
        bool uniform = __all_sync(FULLM, !act || (li == uli));
        unsigned warp_n0 = (unsigned)(n - lane);     // consecutive n within warp
        if (uniform) {
            int cnt = s_cnt[uli], base = uli * KMAX;
            for (int m = 0; m < cnt; m++) {
                int slot = base + m;
                float4 gq = s_bkt[slot];
                unsigned di = 0xffffffffu, dr = 0xffffffffu;
                if (act) {
                    float dxi = __fmul_rn(__fsub_rn(pi.x, gq.x), gq.z);
                    float dyi = __fmul_rn(__fsub_rn(pi.y, gq.y), gq.w);
                    di = __float_as_uint(__fadd_rn(__fmul_rn(dxi, dxi), __fmul_rn(dyi, dyi)));
                    float dxr = __fmul_rn(__fsub_rn(pr.x, gq.x), gq.z);
                    float dyr = __fmul_rn(__fsub_rn(pr.y, gq.y), gq.w);
                    dr = __float_as_uint(__fadd_rn(__fmul_rn(dxr, dxr), __fmul_rn(dyr, dyr)));
                }
                unsigned mi = __reduce_min_sync(FULLM, di);
                unsigned mr = __reduce_min_sync(FULLM, dr);
                unsigned bi = __ballot_sync(FULLM, di == mi);
                unsigned br = __ballot_sync(FULLM, dr == mr);
                if (lane == 0) {
                    unsigned uni_ = warp_n0 + (unsigned)(__ffs(bi) - 1);
                    unsigned unr_ = warp_n0 + (unsigned)(__ffs(br) - 1);
                    atomicMax(&g_best[0][slot], ~(((unsigned long long)mi << 32) | uni_));
                    atomicMax(&g_best[1][slot], ~(((unsigned long long)mr << 32) | unr_));
                }
            }
        } else if (act) {                            // level-boundary warps (rare)
            int cnt = s_cnt[li], base = li * KMAX;
            unsigned un = (unsigned)n;
            for (int m = 0; m < cnt; m++) {
                int slot = base + m;
                float4 gq = s_bkt[slot];
                float dxi = __fmul_rn(__fsub_rn(pi.x, gq.x), gq.z);
                float dyi = __fmul_rn(__fsub_rn(pi.y, gq.y), gq.w);
                float ddi = __fadd_rn(__fmul_rn(dxi, dxi), __fmul_rn(dyi, dyi));
                atomicMax(&g_best[0][slot],
                          ~(((unsigned long long)__float_as_uint(ddi) << 32) | un));
                float dxr = __fmul_rn(__fsub_rn(pr.x, gq.x), gq.z);
                float dyr = __fmul_rn(__fsub_rn(pr.y, gq.y), gq.w);
                float ddr = __fadd_rn(__fmul_rn(dxr, dxr), __fmul_rn(dyr, dyr));
                atomicMax(&g_best[1][slot],
                          ~(((unsigned long long)__float_as_uint(ddr) << 32) | un));
            }
        }
    }
    double lterm = act ? lse_term(cq) : 0.0;
    for (int o = 16; o; o >>= 1) lterm += __shfl_down_sync(FULLM, lterm, o);
    if (lane == 0) s_red[w] = lterm;
    __syncthreads();
    if (tid == 0) {
        double bs = 0.0;
        for (int q = 0; q < NTHR_A / 32; q++) bs += s_red[q];
        g_blk_lse[bid] = bs;
    }
}

// ================= kernel 2: scan replay ONCE (1 block; halves = stages) + corr =================
__global__ void __launch_bounds__(128) k_scan(
    const float* __restrict__ cls, const int* __restrict__ glab, int K)
{
    __shared__ unsigned long long s_cmp[2][KMAX];
    __shared__ int s_j[2][KMAX];
    __shared__ int s_lead[2][KMAX];
    __shared__ int s_cnt[2];
    __shared__ double s_red[2];

    const int tid = threadIdx.x;
    const int s   = tid >> 6;          // 0 or 1 (stage)
    const int t   = tid & 63;          // index within stage

    {
        unsigned long long v = (t < K) ? __ldcg(&g_best[s][__ldg(&g_k2b[t])]) : 0ull;
        bool valid = (v != 0ull);
        unsigned long long pk = ~v;                  // (md_bits<<32)|point_idx
        s_j[s][t]   = valid ? (int)(unsigned)(pk & 0xffffffffu) : (-1 - t);
        s_cmp[s][t] = valid ? (((pk >> 32) << 32) | (unsigned)t) : ~0ull;
    }
    __syncthreads();
    {
        int j = s_j[s][t];
        bool lead = (j >= 0);
        if (lead)
            for (int e = 0; e < t; e++)
                if (s_j[s][e] == j) { lead = false; break; }
        s_lead[s][t] = lead ? 1 : 0;
    }
    __syncthreads();
    if (t < K && s_lead[s][t]) {
        int j = s_j[s][t];
        unsigned long long best = s_cmp[s][t];
        for (int e = 0; e < K; e++)
            if (s_j[s][e] == j && s_cmp[s][e] < best) best = s_cmp[s][e];
        int pos = 0;
        for (int e = 0; e < t; e++) pos += s_lead[s][e];
        g_pos_idx[s][pos] = j;
        g_pos_gt[s][pos]  = (int)(unsigned)(best & 0xffffffffu);
    }
    __syncthreads();
    if (t == 0) {
        int cnt = 0;
        for (int e = 0; e < K; e++) cnt += s_lead[s][e];
        g_cnt01[s] = cnt;
        s_cnt[s] = cnt;
    }
    __syncthreads();

    // stage-1 half computes the cls label correction (parallel gather)
    if (s == 1) {
        double part = 0.0;
        if (t < s_cnt[1]) {
            int j   = g_pos_idx[1][t];
            int lab = glab[g_pos_gt[1][t]];
            part = (double)cls[(size_t)j * 16 + 0] - (double)cls[(size_t)j * 16 + lab];
        }
        for (int o = 16; o; o >>= 1) part += __shfl_down_sync(FULLM, part, o);
        if ((t & 31) == 0) s_red[t >> 5] = part;
        __syncthreads();
        if (t == 0) g_corr_val = s_red[0] + s_red[1];
    } else {
        __syncthreads();
    }
}

// ================= kernel 3: pure geometry, 2-warp blocks (R5-measured fast) =================
__global__ void __launch_bounds__(NTHR_G, 1) k_geom(
    const float* __restrict__ rpi, const float* __restrict__ rpr,
    const float* __restrict__ gtb)
{
    __shared__ float2 sP9[9];
    __shared__ float2 sGT[4];
    __shared__ float2 sG[4];
    __shared__ float2 sPtsB[13];
    __shared__ float2 sVa[BUF], sVb[BUF];
    __shared__ float2 sScrA[BUF];
    __shared__ float  sKeyA[13], sKeyB[13], sKeyG[4];
    __shared__ float  s_apred, s_agt, s_aint, s_ahull;

    const int tid  = threadIdx.x;
    const int bid  = blockIdx.x;
    const int lane = tid & 31;
    const int w    = tid >> 5;
    const int s = (bid >= KMAX) ? 1 : 0;
    const int m = bid - s * KMAX;
    if (m >= g_cnt01[s]) return;

    const float* rp  = s ? rpr : rpi;
    {
        int j  = g_pos_idx[s][m];
        int gi = g_pos_gt[s][m];
        const float* g8  = gtb + 8 * gi;
        const float* p18 = rp + (size_t)j * 18;
        if (tid < 4) {
            float2 c = make_float2(g8[2 * tid], g8[2 * tid + 1]);
            sGT[tid] = c;
            sPtsB[tid] = c;
        }
        if (tid >= 4 && tid < 13) {
            float2 c = make_float2(p18[2 * (tid - 4)], p18[2 * (tid - 4) + 1]);
            sP9[tid - 4] = c;
            sPtsB[tid] = c;
        }
    }
    __syncthreads();

    if (w == 1) {
        // big hull of concat(gt4_original, p9)
        int ch = hull_warp_sorted(sPtsB, 13, sKeyB, sVb, lane);
        if (lane == 0) s_ahull = shoelace16(sVb, ch);
    } else {
        // gt CCW ordering by angle around mean, stable rank (== argsort)
        if (lane < 4) {
            float cmx = (sGT[0].x + sGT[1].x + sGT[2].x + sGT[3].x) * 0.25f;
            float cmy = (sGT[0].y + sGT[1].y + sGT[2].y + sGT[3].y) * 0.25f;
            sKeyG[lane] = atan2f(__fsub_rn(sGT[lane].y, cmy),
                                 __fsub_rn(sGT[lane].x, cmx));
        }
        __syncwarp();
        if (lane < 4) {
            float ki = sKeyG[lane];
            int r = 0;
            #pragma unroll
            for (int j2 = 0; j2 < 4; j2++) {
                float kj = sKeyG[j2];
                r += (kj < ki) || (kj == ki && j2 < lane);
            }
            sG[r] = sGT[lane];
        }
        __syncwarp();
        // pred hull + clip
        int c = hull_warp_sorted(sP9, 9, sKeyA, sVa, lane);
        if (lane == 0) {
            s_apred = shoelace16(sVa, c);
            float sgt = 0.f;
            #pragma unroll
            for (int i = 0; i < 4; i++) {
                int nx = (i + 1 < 4) ? i + 1 : 0;
                sgt = __fadd_rn(sgt, cross_nf(sG[i].x, sG[i].y, sG[nx].x, sG[nx].y));
            }
            s_agt = 0.5f * fabsf(sgt);
        }
        for (int e = 0; e < 4; e++) clip_warp(sVa, c, sG[e], sG[(e + 1) & 3], lane, sScrA);
        if (lane == 0) s_aint = shoelace16(sVa, c);
    }
    __syncthreads();

    if (tid == 0) {
        float uni = __fsub_rn(__fadd_rn(s_apred, s_agt), s_aint);
        float iou = __fdiv_rn(s_aint, __fadd_rn(uni, 1e-16f));
        float giou = __fsub_rn(iou, __fdiv_rn(__fsub_rn(s_ahull, uni),
                                              __fadd_rn(s_ahull, 1e-16f)));
        float gl = __fsub_rn(1.0f, giou);

        // out-of-box penalty (serial: matches reference reduce order)
        float acc = 0.f;
        #pragma unroll
        for (int p = 0; p < 9; p++) {
            float mx = -f_inf();
            #pragma unroll
            for (int e = 0; e < 4; e++) {
                float ex = __fsub_rn(sG[(e + 1) & 3].x, sG[e].x);
                float ey = __fsub_rn(sG[(e + 1) & 3].y, sG[e].y);
                float num = cross_nf(ex, ey, __fsub_rn(sP9[p].x, sG[e].x),
                                             __fsub_rn(sP9[p].y, sG[e].y));
                float sv = __fdiv_rn(num,
                    __fadd_rn(__fsqrt_rn(__fadd_rn(__fmul_rn(ex, ex),
                                                   __fmul_rn(ey, ey))), 1e-9f));
                mx = fmaxf(mx, -sv);
            }
            acc = __fadd_rn(acc, fmaxf(mx, 0.f));
        }
        g_task_gl[s][m]  = (double)gl;
        g_task_oob[s][m] = (double)__fdiv_rn(acc, 9.0f);
    }
}

// ================= kernel 4: final combine + state restore =================
__global__ void k_final(int N, int nblk_a, float* __restrict__ out)
{
    __shared__ double s_tgl[2 * KMAX], s_tob[2 * KMAX];
    __shared__ double s_lse[MAXBLK_A];
    const int tid = threadIdx.x;
    const int nt  = blockDim.x;

    int c0 = __ldcg(&g_cnt01[0]);
    int c1 = __ldcg(&g_cnt01[1]);
    for (int q = tid; q < 2 * KMAX; q += nt) {
        int s2 = q >> 6, mm = q & 63;
        int cs = s2 ? c1 : c0;
        s_tgl[q] = (mm < cs) ? __ldcg(&g_task_gl[s2][mm])  : 0.0;
        s_tob[q] = (mm < cs) ? __ldcg(&g_task_oob[s2][mm]) : 0.0;
    }
    for (int q = tid; q < nblk_a; q += nt) s_lse[q] = __ldcg(&g_blk_lse[q]);
    __syncthreads();
    if (tid == 0) {
        double lse = 0.0;
        for (int q = 0; q < nblk_a; q++) lse += s_lse[q];          // fixed order
        double loc_i = 0.0, sc_i = 0.0, loc_r = 0.0, sc_r = 0.0;
        for (int mm = 0; mm < KMAX; mm++) { loc_i += s_tgl[mm];        sc_i += s_tob[mm]; }
        for (int mm = 0; mm < KMAX; mm++) { loc_r += s_tgl[KMAX + mm]; sc_r += s_tob[KMAX + mm]; }
        double corr = __ldcg(&g_corr_val);
        double cls_loss = (lse + corr) / (double)N;
        double ni = (double)max(c0, 1);
        double nr = (double)max(c1, 1);
        double loss = cls_loss
                    + 0.3  * (loc_i / ni)
                    + 1.0  * (loc_r / nr)
                    + 0.05 * (sc_i / ni)
                    + 0.1  * (sc_r / nr);
        out[0] = (float)loss;
    }
    // restore zero-init g_best for the next (identical) launch
    for (int q = tid; q < NB; q += nt) { g_best[0][q] = 0ull; g_best[1][q] = 0ull; }
}

// ---------------- launch ----------------
extern "C" void kernel_launch(void* const* d_in, const int* in_sizes, int n_in,
                              void* d_out, int out_size)
{
    const float* rpi  = (const float*)d_in[0];
    const float* rpr  = (const float*)d_in[1];
    const float* cls  = (const float*)d_in[2];
    const float* pstr = (const float*)d_in[3];
    const float* gtb  = (const float*)d_in[4];
    const int*   glab = (const int*)d_in[5];
    float* out = (float*)d_out;

    int N = in_sizes[3];          // points_stride element count
    int K = in_sizes[5];          // gt_labels element count (=64)
    if (K > KMAX) K = KMAX;

    int nblk_a = (N + NTHR_A - 1) / NTHR_A;     // one chunk per block
    if (nblk_a > MAXBLK_A) nblk_a = MAXBLK_A;   // (N fits: 98208/256 = 384)

    k_assign<<<nblk_a, NTHR_A>>>(rpi, rpr, cls, pstr, gtb, N, K);
    k_scan<<<1, 128>>>(cls, glab, K);
    k_geom<<<NTASK, NTHR_G>>>(rpi, rpr, gtb);
    k_final<<<1, 256>>>(N, nblk_a, out);
}

// round 17
// speedup vs baseline: 1.6237x; 1.6160x over previous
#include <cuda_runtime.h>
#include <math.h>
#include <stdint.h>

#define KMAX 64
#define BUF  16
#define NLVL 5          // levels 3..7
#define NB   (NLVL * KMAX)
#define NTHR_A 256      // assign block (small => many blocks => dynamic balance)
#define MAXBLK_A 512    // upper bound on assign grid
#define NTHR_G 64       // geom block: 2 warps (R5-measured fastest)
#define NTASK (2 * KMAX)
#define FULLM 0xffffffffu

// ---------------- device-global state (zero-init; g_best restored by k_final) ----------------
__device__ unsigned long long g_best[2][NB];     // INVERTED packed keys; 0 = empty (max-reduced)
__device__ int    g_k2b[KMAX];                   // original k -> bucket slot
__device__ int    g_pos_idx[2][KMAX];
__device__ int    g_pos_gt[2][KMAX];
__device__ int    g_cnt01[2];
__device__ double g_blk_lse[MAXBLK_A];
__device__ double g_corr_val;
__device__ double g_task_gl[2][KMAX];
__device__ double g_task_oob[2][KMAX];

__device__ __forceinline__ float f_inf() { return __int_as_float(0x7f800000); }

// Non-FMA cross product: matches XLA's unfused mul/sub semantics exactly.
__device__ __forceinline__ float cross_nf(float ax, float ay, float bx, float by)
{
    return __fsub_rn(__fmul_rn(ax, by), __fmul_rn(ay, bx));
}

// ---------------- geometry helpers (R5 2-warp versions, bit-exact, measured fast) ----------------
__device__ float shoelace16(const float2* V, int c)
{
    float s = 0.f;
    #pragma unroll
    for (int i = 0; i < BUF; i++) {
        if (i >= c) continue;
        int nxt = (i + 1 < c) ? i + 1 : 0;
        s = __fadd_rn(s, cross_nf(V[i].x, V[i].y, V[nxt].x, V[nxt].y));
    }
    return 0.5f * fabsf(s);
}

// lane-per-vertex membership + stable rank sort; reference semantics, bit-exact
__device__ int hull_warp_sorted(const float2* sP, int n, float* skey, float2* sV, int lane)
{
    bool h = false;
    if (lane < n) {
        float pix = sP[lane].x, piy = sP[lane].y;
        for (int j = 0; j < n && !h; j++) {
            if (j == lane) continue;
            float dx = __fsub_rn(sP[j].x, pix), dy = __fsub_rn(sP[j].y, piy);
            float mn = f_inf();
            for (int k = 0; k < n; k++) {
                float cr = cross_nf(dx, dy, __fsub_rn(sP[k].x, pix), __fsub_rn(sP[k].y, piy));
                mn = fminf(mn, cr);            // min: order-independent
            }
            if (mn >= -1e-6f) h = true;
        }
    }
    unsigned mask = __ballot_sync(FULLM, h);
    int cnt = __popc(mask);
    float sx = 0.f, sy = 0.f;
    for (int i = 0; i < n; i++)
        if ((mask >> i) & 1) { sx = __fadd_rn(sx, sP[i].x); sy = __fadd_rn(sy, sP[i].y); }
    float cd = (float)(cnt > 0 ? cnt : 1);
    float cenx = __fdiv_rn(sx, cd), ceny = __fdiv_rn(sy, cd);
    if (lane < n)
        skey[lane] = h ? atan2f(__fsub_rn(sP[lane].y, ceny), __fsub_rn(sP[lane].x, cenx))
                       : f_inf();
    __syncwarp();
    if (lane < n) {                                    // stable rank == argsort
        float ki = skey[lane];
        int r = 0;
        for (int j = 0; j < n; j++) {
            float kj = skey[j];
            r += (kj < ki) || (kj == ki && j < lane);
        }
        sV[r] = sP[lane];
    }
    if (lane >= n && lane < BUF) sV[lane] = make_float2(0.f, 0.f);
    __syncwarp();
    return cnt;
}

__device__ void clip_warp(float2* V, int& c, float2 a, float2 b, int lane, float2* scratch)
{
    float ex = __fsub_rn(b.x, a.x), ey = __fsub_rn(b.y, a.y);
    int cc = c;
    bool active = (lane < BUF) && (lane < cc);
    int nxt = (lane + 1 < cc) ? lane + 1 : 0;
    float2 cur = active ? V[lane] : make_float2(0.f, 0.f);
    float2 nx  = active ? V[nxt]  : make_float2(0.f, 0.f);
    float s_cur = cross_nf(ex, ey, __fsub_rn(cur.x, a.x), __fsub_rn(cur.y, a.y));
    float s_nxt = cross_nf(ex, ey, __fsub_rn(nx.x,  a.x), __fsub_rn(nx.y,  a.y));
    bool in_cur = s_cur >= 0.f, in_nxt = s_nxt >= 0.f;
    float den = __fsub_rn(s_cur, s_nxt);
    float t = (fabsf(den) > 1e-9f) ? __fdiv_rn(s_cur, den) : 0.f;
    float2 ipt = make_float2(__fadd_rn(cur.x, __fmul_rn(t, __fsub_rn(nx.x, cur.x))),
                             __fadd_rn(cur.y, __fmul_rn(t, __fsub_rn(nx.y, cur.y))));
    bool f_int = active && (in_cur != in_nxt);
    bool f_nxt = active && in_nxt;
    unsigned bi = __ballot_sync(FULLM, f_int);
    unsigned bn = __ballot_sync(FULLM, f_nxt);
    unsigned below = (1u << lane) - 1u;
    int pos_i = __popc(bi & below) + __popc(bn & below);
    int pos_n = pos_i + (f_int ? 1 : 0);
    int nc = __popc(bi) + __popc(bn);
    __syncwarp();
    if (f_int && pos_i < BUF) scratch[pos_i] = ipt;
    if (f_nxt && pos_n < BUF) scratch[pos_n] = nx;
    __syncwarp();
    if (lane < BUF) V[lane] = (lane < nc) ? scratch[lane] : make_float2(0.f, 0.f);
    __syncwarp();
    c = nc;
}

__device__ __forceinline__ double lse_term(const float4* c4q)
{
    float v[16];
    #pragma unroll
    for (int j = 0; j < 4; j++) {
        float4 f = c4q[j];
        v[4 * j] = f.x; v[4 * j + 1] = f.y; v[4 * j + 2] = f.z; v[4 * j + 3] = f.w;
    }
    float mm = v[0];
    #pragma unroll
    for (int j = 1; j < 16; j++) mm = fmaxf(mm, v[j]);
    float ss = 0.f;
    #pragma unroll
    for (int j = 0; j < 16; j++) ss += __expf(v[j] - mm);
    return (double)((mm + __logf(ss)) - v[0]);
}

// ================= kernel 1: prep + assign + cls logsumexp (R14 verbatim) =================
__global__ void __launch_bounds__(NTHR_A) k_assign(
    const float* __restrict__ rpi, const float* __restrict__ rpr,
    const float* __restrict__ cls, const float* __restrict__ pstr,
    const float* __restrict__ gtb, int N, int K)
{
    __shared__ float  s_cx[KMAX], s_cy[KMAX], s_rw[KMAX], s_rh[KMAX];
    __shared__ int    s_lvl[KMAX];
    __shared__ float4 s_bkt[NB];
    __shared__ int    s_k2b[KMAX];
    __shared__ int    s_cnt[NLVL];
    __shared__ double s_red[NTHR_A / 32];

    const int tid  = threadIdx.x;
    const int bid  = blockIdx.x;
    const int lane = tid & 31;
    const int w    = tid >> 5;

    if (tid < K) {
        const float* r = gtb + 8 * tid;
        float xmn = fminf(fminf(r[0], r[2]), fminf(r[4], r[6]));
        float xmx = fmaxf(fmaxf(r[0], r[2]), fmaxf(r[4], r[6]));
        float ymn = fminf(fminf(r[1], r[3]), fminf(r[5], r[7]));
        float ymx = fmaxf(fmaxf(r[1], r[3]), fmaxf(r[5], r[7]));
        float ww = fmaxf(__fsub_rn(xmx, xmn), 1e-6f);
        float hh = fmaxf(__fsub_rn(ymx, ymn), 1e-6f);
        s_cx[tid] = __fmul_rn(__fadd_rn(xmn, xmx), 0.5f);
        s_cy[tid] = __fmul_rn(__fadd_rn(ymn, ymx), 0.5f);
        s_rw[tid] = __fdiv_rn(1.0f, ww);
        s_rh[tid] = __fdiv_rn(1.0f, hh);
        float lv = __fmul_rn(__fadd_rn(log2f(__fdiv_rn(ww, 4.0f)),
                                       log2f(__fdiv_rn(hh, 4.0f))), 0.5f);
        int lvl = (int)lv;
        s_lvl[tid] = max(3, min(7, lvl));
    }
    __syncthreads();
    if (tid == 0) {                                  // serial bucket build, ascending k
        int cnt[NLVL];
        #pragma unroll
        for (int l = 0; l < NLVL; l++) cnt[l] = 0;
        for (int q = 0; q < K; q++) {
            int li = s_lvl[q] - 3;
            int slot = li * KMAX + cnt[li];
            s_bkt[slot] = make_float4(s_cx[q], s_cy[q], s_rw[q], s_rh[q]);
            s_k2b[q] = slot;
            cnt[li]++;
        }
        #pragma unroll
        for (int l = 0; l < NLVL; l++) s_cnt[l] = cnt[l];
    }
    __syncthreads();
    if (bid == 0 && tid < K) g_k2b[tid] = s_k2b[tid];   // publish map for k_scan

    const int n = bid * NTHR_A + tid;
    const bool act = (n < N);
    const int i0 = act ? n : 0;

    // hoisted loads (clamped): stream while the gt loop computes
    float  st = __ldg(pstr + i0);
    float2 pi = __ldg((const float2*)(rpi + (size_t)i0 * 18 + 8));
    float2 pr = __ldg((const float2*)(rpr + (size_t)i0 * 18 + 8));
    float4 cq[4];
    {
        const float4* q = (const float4*)(cls + (size_t)i0 * 16);
        #pragma unroll
        for (int j = 0; j < 4; j++) cq[j] = __ldg(q + j);
    }
    int li = (31 - __clz((int)st)) - 3;

    unsigned actmask = __ballot_sync(FULLM, act);
    if (actmask) {
        int src0 = __ffs(actmask) - 1;
        int uli = __shfl_sync(FULLM, li, src0);
        bool uniform = __all_sync(FULLM, !act || (li == uli));
        unsigned warp_n0 = (unsigned)(n - lane);     // consecutive n within warp
        if (uniform) {
            int cnt = s_cnt[uli], base = uli * KMAX;
            for (int m = 0; m < cnt; m++) {
                int slot = base + m;
                float4 gq = s_bkt[slot];
                unsigned di = 0xffffffffu, dr = 0xffffffffu;
                if (act) {
                    float dxi = __fmul_rn(__fsub_rn(pi.x, gq.x), gq.z);
                    float dyi = __fmul_rn(__fsub_rn(pi.y, gq.y), gq.w);
                    di = __float_as_uint(__fadd_rn(__fmul_rn(dxi, dxi), __fmul_rn(dyi, dyi)));
                    float dxr = __fmul_rn(__fsub_rn(pr.x, gq.x), gq.z);
                    float dyr = __fmul_rn(__fsub_rn(pr.y, gq.y), gq.w);
                    dr = __float_as_uint(__fadd_rn(__fmul_rn(dxr, dxr), __fmul_rn(dyr, dyr)));
                }
                unsigned mi = __reduce_min_sync(FULLM, di);
                unsigned mr = __reduce_min_sync(FULLM, dr);
                unsigned bi = __ballot_sync(FULLM, di == mi);
                unsigned br = __ballot_sync(FULLM, dr == mr);
                if (lane == 0) {
                    unsigned uni_ = warp_n0 + (unsigned)(__ffs(bi) - 1);
                    unsigned unr_ = warp_n0 + (unsigned)(__ffs(br) - 1);
                    atomicMax(&g_best[0][slot], ~(((unsigned long long)mi << 32) | uni_));
                    atomicMax(&g_best[1][slot], ~(((unsigned long long)mr << 32) | unr_));
                }
            }
        } else if (act) {                            // level-boundary warps (rare)
            int cnt = s_cnt[li], base = li * KMAX;
            unsigned un = (unsigned)n;
            for (int m = 0; m < cnt; m++) {
                int slot = base + m;
                float4 gq = s_bkt[slot];
                float dxi = __fmul_rn(__fsub_rn(pi.x, gq.x), gq.z);
                float dyi = __fmul_rn(__fsub_rn(pi.y, gq.y), gq.w);
                float ddi = __fadd_rn(__fmul_rn(dxi, dxi), __fmul_rn(dyi, dyi));
                atomicMax(&g_best[0][slot],
                          ~(((unsigned long long)__float_as_uint(ddi) << 32) | un));
                float dxr = __fmul_rn(__fsub_rn(pr.x, gq.x), gq.z);
                float dyr = __fmul_rn(__fsub_rn(pr.y, gq.y), gq.w);
                float ddr = __fadd_rn(__fmul_rn(dxr, dxr), __fmul_rn(dyr, dyr));
                atomicMax(&g_best[1][slot],
                          ~(((unsigned long long)__float_as_uint(ddr) << 32) | un));
            }
        }
    }
    double lterm = act ? lse_term(cq) : 0.0;
    for (int o = 16; o; o >>= 1) lterm += __shfl_down_sync(FULLM, lterm, o);
    if (lane == 0) s_red[w] = lterm;
    __syncthreads();
    if (tid == 0) {
        double bs = 0.0;
        for (int q = 0; q < NTHR_A / 32; q++) bs += s_red[q];
        g_blk_lse[bid] = bs;
    }
}

// ================= kernel 2: scan replay ONCE (1 block; halves = stages) + corr =================
__global__ void __launch_bounds__(128) k_scan(
    const float* __restrict__ cls, const int* __restrict__ glab, int K)
{
    __shared__ unsigned long long s_cmp[2][KMAX];
    __shared__ int s_j[2][KMAX];
    __shared__ int s_lead[2][KMAX];
    __shared__ int s_cnt[2];
    __shared__ double s_red[2];

    const int tid = threadIdx.x;
    const int s   = tid >> 6;          // 0 or 1 (stage)
    const int t   = tid & 63;          // index within stage

    {
        unsigned long long v = (t < K) ? __ldcg(&g_best[s][__ldg(&g_k2b[t])]) : 0ull;
        bool valid = (v != 0ull);
        unsigned long long pk = ~v;                  // (md_bits<<32)|point_idx
        s_j[s][t]   = valid ? (int)(unsigned)(pk & 0xffffffffu) : (-1 - t);
        s_cmp[s][t] = valid ? (((pk >> 32) << 32) | (unsigned)t) : ~0ull;
    }
    __syncthreads();
    {
        int j = s_j[s][t];
        bool lead = (j >= 0);
        if (lead)
            for (int e = 0; e < t; e++)
                if (s_j[s][e] == j) { lead = false; break; }
        s_lead[s][t] = lead ? 1 : 0;
    }
    __syncthreads();
    if (t < K && s_lead[s][t]) {
        int j = s_j[s][t];
        unsigned long long best = s_cmp[s][t];
        for (int e = 0; e < K; e++)
            if (s_j[s][e] == j && s_cmp[s][e] < best) best = s_cmp[s][e];
        int pos = 0;
        for (int e = 0; e < t; e++) pos += s_lead[s][e];
        g_pos_idx[s][pos] = j;
        g_pos_gt[s][pos]  = (int)(unsigned)(best & 0xffffffffu);
    }
    __syncthreads();
    if (t == 0) {
        int cnt = 0;
        for (int e = 0; e < K; e++) cnt += s_lead[s][e];
        g_cnt01[s] = cnt;
        s_cnt[s] = cnt;
    }
    __syncthreads();

    // stage-1 half computes the cls label correction (parallel gather)
    if (s == 1) {
        double part = 0.0;
        if (t < s_cnt[1]) {
            int j   = g_pos_idx[1][t];
            int lab = glab[g_pos_gt[1][t]];
            part = (double)cls[(size_t)j * 16 + 0] - (double)cls[(size_t)j * 16 + lab];
        }
        for (int o = 16; o; o >>= 1) part += __shfl_down_sync(FULLM, part, o);
        if ((t & 31) == 0) s_red[t >> 5] = part;
        __syncthreads();
        if (t == 0) g_corr_val = s_red[0] + s_red[1];
    } else {
        __syncthreads();
    }
}

// ================= kernel 3: pure geometry, 2-warp blocks (R5-measured fast) =================
__global__ void __launch_bounds__(NTHR_G, 1) k_geom(
    const float* __restrict__ rpi, const float* __restrict__ rpr,
    const float* __restrict__ gtb)
{
    __shared__ float2 sP9[9];
    __shared__ float2 sGT[4];
    __shared__ float2 sG[4];
    __shared__ float2 sPtsB[13];
    __shared__ float2 sVa[BUF], sVb[BUF];
    __shared__ float2 sScrA[BUF];
    __shared__ float  sKeyA[13], sKeyB[13], sKeyG[4];
    __shared__ float  s_apred, s_agt, s_aint, s_ahull;

    const int tid  = threadIdx.x;
    const int bid  = blockIdx.x;
    const int lane = tid & 31;
    const int w    = tid >> 5;
    const int s = (bid >= KMAX) ? 1 : 0;
    const int m = bid - s * KMAX;
    if (m >= g_cnt01[s]) return;

    const float* rp  = s ? rpr : rpi;
    {
        int j  = g_pos_idx[s][m];
        int gi = g_pos_gt[s][m];
        const float* g8  = gtb + 8 * gi;
        const float* p18 = rp + (size_t)j * 18;
        if (tid < 4) {
            float2 c = make_float2(g8[2 * tid], g8[2 * tid + 1]);
            sGT[tid] = c;
            sPtsB[tid] = c;
        }
        if (tid >= 4 && tid < 13) {
            float2 c = make_float2(p18[2 * (tid - 4)], p18[2 * (tid - 4) + 1]);
            sP9[tid - 4] = c;
            sPtsB[tid] = c;
        }
    }
    __syncthreads();

    if (w == 1) {
        // big hull of concat(gt4_original, p9)
        int ch = hull_warp_sorted(sPtsB, 13, sKeyB, sVb, lane);
        if (lane == 0) s_ahull = shoelace16(sVb, ch);
    } else {
        // gt CCW ordering by angle around mean, stable rank (== argsort)
        if (lane < 4) {
            float cmx = (sGT[0].x + sGT[1].x + sGT[2].x + sGT[3].x) * 0.25f;
            float cmy = (sGT[0].y + sGT[1].y + sGT[2].y + sGT[3].y) * 0.25f;
            sKeyG[lane] = atan2f(__fsub_rn(sGT[lane].y, cmy),
                                 __fsub_rn(sGT[lane].x, cmx));
        }
        __syncwarp();
        if (lane < 4) {
            float ki = sKeyG[lane];
            int r = 0;
            #pragma unroll
            for (int j2 = 0; j2 < 4; j2++) {
                float kj = sKeyG[j2];
                r += (kj < ki) || (kj == ki && j2 < lane);
            }
            sG[r] = sGT[lane];
        }
        __syncwarp();
        // pred hull + clip
        int c = hull_warp_sorted(sP9, 9, sKeyA, sVa, lane);
        if (lane == 0) {
            s_apred = shoelace16(sVa, c);
            float sgt = 0.f;
            #pragma unroll
            for (int i = 0; i < 4; i++) {
                int nx = (i + 1 < 4) ? i + 1 : 0;
                sgt = __fadd_rn(sgt, cross_nf(sG[i].x, sG[i].y, sG[nx].x, sG[nx].y));
            }
            s_agt = 0.5f * fabsf(sgt);
        }
        for (int e = 0; e < 4; e++) clip_warp(sVa, c, sG[e], sG[(e + 1) & 3], lane, sScrA);
        if (lane == 0) s_aint = shoelace16(sVa, c);
    }
    __syncthreads();

    if (tid == 0) {
        float uni = __fsub_rn(__fadd_rn(s_apred, s_agt), s_aint);
        float iou = __fdiv_rn(s_aint, __fadd_rn(uni, 1e-16f));
        float giou = __fsub_rn(iou, __fdiv_rn(__fsub_rn(s_ahull, uni),
                                              __fadd_rn(s_ahull, 1e-16f)));
        float gl = __fsub_rn(1.0f, giou);

        // out-of-box penalty (serial: matches reference reduce order)
        float acc = 0.f;
        #pragma unroll
        for (int p = 0; p < 9; p++) {
            float mx = -f_inf();
            #pragma unroll
            for (int e = 0; e < 4; e++) {
                float ex = __fsub_rn(sG[(e + 1) & 3].x, sG[e].x);
                float ey = __fsub_rn(sG[(e + 1) & 3].y, sG[e].y);
                float num = cross_nf(ex, ey, __fsub_rn(sP9[p].x, sG[e].x),
                                             __fsub_rn(sP9[p].y, sG[e].y));
                float sv = __fdiv_rn(num,
                    __fadd_rn(__fsqrt_rn(__fadd_rn(__fmul_rn(ex, ex),
                                                   __fmul_rn(ey, ey))), 1e-9f));
                mx = fmaxf(mx, -sv);
            }
            acc = __fadd_rn(acc, fmaxf(mx, 0.f));
        }
        g_task_gl[s][m]  = (double)gl;
        g_task_oob[s][m] = (double)__fdiv_rn(acc, 9.0f);
    }
}

// ================= kernel 4: final combine, PARALLEL double reductions =================
// (old version summed ~650 doubles in a serial dependent chain on one thread:
//  ~650 x ~47cyc fp64-add latency ≈ 30us. Warp-tree reduction cuts the chain to ~15 adds.)
__global__ void __launch_bounds__(256) k_final(int N, int nblk_a, float* __restrict__ out)
{
    __shared__ double s_part[8];
    const int tid  = threadIdx.x;
    const int lane = tid & 31;
    const int w    = tid >> 5;

    int c0 = __ldcg(&g_cnt01[0]);
    int c1 = __ldcg(&g_cnt01[1]);

    double p = 0.0;
    if (w < 4) {
        // lse partials over nblk_a, strided across 128 threads (warps 0-3)
        for (int q = tid; q < nblk_a; q += 128) p += __ldcg(&g_blk_lse[q]);
    } else if (w == 4) {
        for (int q = lane; q < c0; q += 32) p += __ldcg(&g_task_gl[0][q]);
    } else if (w == 5) {
        for (int q = lane; q < c0; q += 32) p += __ldcg(&g_task_oob[0][q]);
    } else if (w == 6) {
        for (int q = lane; q < c1; q += 32) p += __ldcg(&g_task_gl[1][q]);
    } else {
        for (int q = lane; q < c1; q += 32) p += __ldcg(&g_task_oob[1][q]);
    }
    for (int o = 16; o; o >>= 1) p += __shfl_down_sync(FULLM, p, o);
    if (lane == 0) s_part[w] = p;
    __syncthreads();

    if (tid == 0) {
        double lse   = s_part[0] + s_part[1] + s_part[2] + s_part[3];
        double loc_i = s_part[4], sc_i = s_part[5];
        double loc_r = s_part[6], sc_r = s_part[7];
        double corr = __ldcg(&g_corr_val);
        double cls_loss = (lse + corr) / (double)N;
        double ni = (double)max(c0, 1);
        double nr = (double)max(c1, 1);
        double loss = cls_loss
                    + 0.3  * (loc_i / ni)
                    + 1.0  * (loc_r / nr)
                    + 0.05 * (sc_i / ni)
                    + 0.1  * (sc_r / nr);
        out[0] = (float)loss;
    }
    // restore zero-init g_best for the next (identical) launch
    for (int q = tid; q < NB; q += 256) { g_best[0][q] = 0ull; g_best[1][q] = 0ull; }
}

// ---------------- launch ----------------
extern "C" void kernel_launch(void* const* d_in, const int* in_sizes, int n_in,
                              void* d_out, int out_size)
{
    const float* rpi  = (const float*)d_in[0];
    const float* rpr  = (const float*)d_in[1];
    const float* cls  = (const float*)d_in[2];
    const float* pstr = (const float*)d_in[3];
    const float* gtb  = (const float*)d_in[4];
    const int*   glab = (const int*)d_in[5];
    float* out = (float*)d_out;

    int N = in_sizes[3];          // points_stride element count
    int K = in_sizes[5];          // gt_labels element count (=64)
    if (K > KMAX) K = KMAX;

    int nblk_a = (N + NTHR_A - 1) / NTHR_A;     // one chunk per block
    if (nblk_a > MAXBLK_A) nblk_a = MAXBLK_A;   // (N fits: 98208/256 = 384)

    k_assign<<<nblk_a, NTHR_A>>>(rpi, rpr, cls, pstr, gtb, N, K);
    k_scan<<<1, 128>>>(cls, glab, K);
    k_geom<<<NTASK, NTHR_G>>>(rpi, rpr, gtb);
    k_final<<<1, 256>>>(N, nblk_a, out);
}